// round 15
// baseline (speedup 1.0000x reference)
#include <cuda_runtime.h>

#define BATCH 4096
#define TSEQ  20
#define INSZ  512
#define HSZ   512
#define RNK   20
#define G4    2048
#define NB    56          // batch rows per sub-tile
#define NB2   28          // batch pairs per sub-tile
#define JT    128         // j columns per block
#define NJT   4
#define NBC   37
#define NBLK  (NJT * NBC) // 148 persistent blocks, all resident
#define HS2   129         // ht2 row stride (float2 units)
#define XCH   64          // kPre k-chunk
#define XSTR  68          // kPre xt row stride (floats; 16B-aligned, conflict-free)

// Scratch (no allocations allowed -> device globals)
__device__ float g_u[TSEQ * RNK * BATCH];        // [t][r][b]
__device__ float g_hu[2][RNK * NJT * BATCH];     // [parity][r][jt][b]
__device__ unsigned g_bar;

typedef unsigned long long ull;

__device__ __forceinline__ void ffma2(ull &d, ull a, ull b) {
    asm("fma.rn.f32x2 %0, %1, %2, %0;" : "+l"(d) : "l"(a), "l"(b));
}
__device__ __forceinline__ ull add2(ull a, ull b) {
    ull d; asm("add.rn.f32x2 %0, %1, %2;" : "=l"(d) : "l"(a), "l"(b)); return d;
}
__device__ __forceinline__ ull pack2(float x, float y) {
    ull r; asm("mov.b64 %0, {%1, %2};" : "=l"(r) : "f"(x), "f"(y)); return r;
}
__device__ __forceinline__ float2 unpack2(ull v) {
    float2 f; asm("mov.b64 {%0, %1}, %2;" : "=f"(f.x), "=f"(f.y) : "l"(v)); return f;
}
__device__ __forceinline__ float tanha(float x) {
    float y; asm("tanh.approx.f32 %0, %1;" : "=f"(y) : "f"(x)); return y;
}
__device__ __forceinline__ float siga(float x) {
    return fmaf(tanha(0.5f * x), 0.5f, 0.5f);
}
__device__ __forceinline__ void bar_arrive(unsigned* p) {
    asm volatile("red.release.gpu.global.add.u32 [%0], 1;" :: "l"(p) : "memory");
}
__device__ __forceinline__ unsigned bar_peek(unsigned* p) {
    unsigned v;
    asm volatile("ld.acquire.gpu.global.u32 %0, [%1];" : "=r"(v) : "l"(p) : "memory");
    return v;
}

// ---------------------------------------------------------------------------
// kPre: u[t][r][b] = sum_k x[b][t][k] * wa[k][r]
// Block = one t x 256 consecutive b; k-chunks of 64 staged coalesced in smem.
// smem = 256*68 + 64*20 = 18688 floats = 74752 B -> 3 blocks/SM, 320 blocks = 1 wave.
#define KPRE_SMEM_FLOATS (256 * XSTR + XCH * RNK)

__global__ __launch_bounds__(256) void kPre(const float* __restrict__ x,
                                            const float* __restrict__ wa) {
    if (blockIdx.x == 0 && threadIdx.x == 0) g_bar = 0u;

    extern __shared__ __align__(16) float smp[];
    float* xt  = smp;                   // [256][XSTR]
    float* wch = smp + 256 * XSTR;      // [XCH][RNK]

    const int tid = threadIdx.x;
    const int t  = blockIdx.x >> 4;           // 16 blocks per t
    const int b0 = (blockIdx.x & 15) * 256;
    const float* xbase = x + ((long)b0 * TSEQ + t) * INSZ;

    ull acc[10];
#pragma unroll
    for (int q = 0; q < 10; q++) acc[q] = 0ull;

    for (int c = 0; c < INSZ / XCH; c++) {
        __syncthreads();    // xt & wch free
        // ---- coalesced x load: 16 lanes cover 256B of one row ----
#pragma unroll
        for (int i = 0; i < 16; i++) {
            int idx = i * 256 + tid;          // float4 slot in [0, 4096)
            int row = idx >> 4, col4 = idx & 15;
            float4 v = *reinterpret_cast<const float4*>(
                xbase + (long)row * (TSEQ * INSZ) + c * XCH + col4 * 4);
            *reinterpret_cast<float4*>(xt + row * XSTR + col4 * 4) = v;
        }
        // ---- was chunk: wch[k][r] (coalesced) ----
#pragma unroll
        for (int i = 0; i < 5; i++) {
            int idx = i * 256 + tid;          // [0, 1280)
            wch[idx] = wa[c * XCH * RNK + idx];
        }
        __syncthreads();
        // ---- compute: thread owns row tid ----
#pragma unroll 4
        for (int k4 = 0; k4 < XCH / 4; k4++) {
            float4 xv = *reinterpret_cast<const float4*>(xt + tid * XSTR + k4 * 4);
#pragma unroll
            for (int i = 0; i < 4; i++) {
                float kv = (i == 0) ? xv.x : (i == 1) ? xv.y : (i == 2) ? xv.z : xv.w;
                ull ks = pack2(kv, kv);
                const ulonglong2* w2 = reinterpret_cast<const ulonglong2*>(
                    wch + (k4 * 4 + i) * RNK);
#pragma unroll
                for (int q = 0; q < 5; q++) {
                    ulonglong2 wv = w2[q];
                    ffma2(acc[2 * q + 0], ks, wv.x);
                    ffma2(acc[2 * q + 1], ks, wv.y);
                }
            }
        }
    }
    const int b = b0 + tid;
#pragma unroll
    for (int q = 0; q < 10; q++) {
        float2 f = unpack2(acc[q]);
        g_u[(t * RNK + 2 * q + 0) * BATCH + b] = f.x;
        g_u[(t * RNK + 2 * q + 1) * BATCH + b] = f.y;
    }
}

// ---------------------------------------------------------------------------
// kStep smem partition (floats)
#define WT_OFF   0
#define WT_SZ    (40 * 512)                 // wT[k][gate*128+jjl]  (persistent)
#define VS_OFF   (WT_OFF + WT_SZ)
#define VS_SZ    (40 * NB2 * 2)             // 2240: vsp2[k][bb2] ull (true pairs)
#define BS_OFF   (VS_OFF + VS_SZ)
#define BS_SZ    512                        // bias (persistent)
#define HT_OFF   (BS_OFF + BS_SZ)
#define HT_SZ    (NB2 * HS2 * 2)            // 7224: ht2[bb2][jjl] float2
#define WA_OFF   (HT_OFF + HT_SZ)
#define WA_SZ    (JT * RNK)                 // 2560: wa[j][r]  (persistent)
#define CS_OFF   (WA_OFF + WA_SZ)
#define CS_SZ    (2 * NB2 * JT * 2)         // 14336: c as float2 pairs, both subs
#define PR_OFF   (CS_OFF + CS_SZ)
#define PR_SZ    (40 * NB * 2)              // 4480: hu partials (ull)
#define SMEM_FLOATS (PR_OFF + PR_SZ)        // 51872 floats = 207488 B -> 1 block/SM

template<int K0, int K1>
__device__ __forceinline__ void gemm_part(ull (&acc)[4][7], const float* wT,
                                          const ull* vsp2, int jjl, int nt) {
#pragma unroll 4
    for (int k = K0; k < K1; k++) {
        float w0 = wT[k * 512 + 0 * 128 + jjl];
        float w1 = wT[k * 512 + 1 * 128 + jjl];
        float w2 = wT[k * 512 + 2 * 128 + jjl];
        float w3 = wT[k * 512 + 3 * 128 + jjl];
        ull wg[4] = {pack2(w0, w0), pack2(w1, w1), pack2(w2, w2), pack2(w3, w3)};
        ull vn[7];
#pragma unroll
        for (int n = 0; n < 7; n++) vn[n] = vsp2[k * NB2 + nt * 7 + n];
#pragma unroll
        for (int g = 0; g < 4; g++)
#pragma unroll
            for (int n = 0; n < 7; n++)
                ffma2(acc[g][n], wg[g], vn[n]);
    }
}

__global__ __launch_bounds__(512, 1) void kStep(
    const float* __restrict__ wih_b, const float* __restrict__ b_ih,
    const float* __restrict__ whh_a, const float* __restrict__ whh_b,
    const float* __restrict__ b_hh,
    float* __restrict__ out,
    float* __restrict__ hdst, float* __restrict__ cdst) {

    extern __shared__ __align__(16) float sm[];
    float* wT   = sm + WT_OFF;
    ull*   vsp2 = reinterpret_cast<ull*>(sm + VS_OFF);
    float* bs   = sm + BS_OFF;
    float2* ht2 = reinterpret_cast<float2*>(sm + HT_OFF);
    float* wa   = sm + WA_OFF;
    float2* cs2 = reinterpret_cast<float2*>(sm + CS_OFF);
    ull*   prt  = reinterpret_cast<ull*>(sm + PR_OFF);

    const int tid = threadIdx.x;
    const int jt = blockIdx.x & 3, bc = blockIdx.x >> 2;   // 4 x 37
    const int j0 = jt * JT;
    const int jjl = tid & 127, nt = tid >> 7;              // 128 x 4

    // ======== one-time staging ========
#pragma unroll
    for (int it = 0; it < 10; it++) {
        int idx4 = it * 512 + tid;
        int r = idx4 >> 7;
        int q = idx4 & 127;
        int gate = q >> 5, jjl4 = q & 31;
        const float* src = (r < RNK) ? (wih_b + r * G4) : (whh_b + (r - RNK) * G4);
        float4 v = reinterpret_cast<const float4*>(src + gate * 512 + j0)[jjl4];
        reinterpret_cast<float4*>(wT + r * 512 + gate * 128)[jjl4] = v;
    }
    {
        int gate = tid >> 7, jjlx = tid & 127;
        int col = gate * 512 + j0 + jjlx;
        bs[tid] = b_ih[col] + b_hh[col];
    }
    for (int idx = tid; idx < (JT * RNK) / 4; idx += 512)
        reinterpret_cast<float4*>(wa)[idx] =
            reinterpret_cast<const float4*>(whh_a + j0 * RNK)[idx];
    __syncthreads();

    // bias splats (constant over time loop)
    ull bgu[4];
#pragma unroll
    for (int g = 0; g < 4; g++) {
        float bv = bs[g * 128 + jjl];
        bgu[g] = pack2(bv, bv);
    }

    // ======== time loop ========
    for (int t = 0; t < TSEQ; t++) {
        const float* rd = g_hu[t & 1];
        float*       wr = g_hu[(t + 1) & 1];
        const bool lastT = (t == TSEQ - 1);

#pragma unroll 1
        for (int sub = 0; sub < 2; sub++) {
            const int b0 = bc * (2 * NB) + sub * NB;
            float2* csub = cs2 + sub * (NB2 * JT);

            // ---- stage u pairs (vsp2 rows 0..19) ----
            for (int idx = tid; idx < RNK * 32; idx += 512) {
                int r = idx >> 5, bb2 = idx & 31;
                if (bb2 < NB2) {
                    int b = b0 + 2 * bb2;
                    float2 v = make_float2(0.f, 0.f);
                    if (b < BATCH)
                        v = *reinterpret_cast<const float2*>(
                            &g_u[(t * RNK + r) * BATCH + b]);
                    vsp2[r * NB2 + bb2] = pack2(v.x, v.y);
                }
            }
            if (sub == 1) {
                for (int idx = tid; idx < RNK * 32; idx += 512) {
                    int r = idx >> 5, bb2 = idx & 31;
                    if (bb2 < NB2) {
                        int b = b0 + 2 * bb2;
                        float2 v = make_float2(0.f, 0.f);
                        if (t > 0 && b < BATCH) {
                            const float2* p = reinterpret_cast<const float2*>(
                                rd + r * (NJT * BATCH) + b);
                            float2 q0 = __ldcg(p);
                            float2 q1 = __ldcg(p + BATCH / 2);
                            float2 q2 = __ldcg(p + BATCH);
                            float2 q3 = __ldcg(p + 3 * BATCH / 2);
                            v = make_float2((q0.x + q1.x) + (q2.x + q3.x),
                                            (q0.y + q1.y) + (q2.y + q3.y));
                        }
                        vsp2[(RNK + r) * NB2 + bb2] = pack2(v.x, v.y);
                    }
                }
            }
            __syncthreads();

            // ---- GEMM (sub0: split around grid barrier; sub1: full) ----
            ull acc[4][7];
#pragma unroll
            for (int g = 0; g < 4; g++)
#pragma unroll
                for (int n = 0; n < 7; n++) acc[g][n] = bgu[g];

            if (sub == 0) {
                gemm_part<0, RNK>(acc, wT, vsp2, jjl, nt);   // u half, hides barrier
                if (t > 0 && tid == 0) {
                    unsigned target = (unsigned)NBLK * (unsigned)t;
                    while (bar_peek(&g_bar) < target) __nanosleep(64);
                }
                __syncthreads();
                // stage hu pairs (vsp2 rows 20..39)
                for (int idx = tid; idx < RNK * 32; idx += 512) {
                    int r = idx >> 5, bb2 = idx & 31;
                    if (bb2 < NB2) {
                        int b = b0 + 2 * bb2;
                        float2 v = make_float2(0.f, 0.f);
                        if (t > 0 && b < BATCH) {
                            const float2* p = reinterpret_cast<const float2*>(
                                rd + r * (NJT * BATCH) + b);
                            float2 q0 = __ldcg(p);
                            float2 q1 = __ldcg(p + BATCH / 2);
                            float2 q2 = __ldcg(p + BATCH);
                            float2 q3 = __ldcg(p + 3 * BATCH / 2);
                            v = make_float2((q0.x + q1.x) + (q2.x + q3.x),
                                            (q0.y + q1.y) + (q2.y + q3.y));
                        }
                        vsp2[(RNK + r) * NB2 + bb2] = pack2(v.x, v.y);
                    }
                }
                __syncthreads();
                gemm_part<RNK, 2 * RNK>(acc, wT, vsp2, jjl, nt);
            } else {
                gemm_part<0, 2 * RNK>(acc, wT, vsp2, jjl, nt);
            }

            // ---- epilogue: cell update over 7 (b, b+1) pairs ----
#pragma unroll
            for (int np = 0; np < 7; np++) {
                int bb2 = nt * 7 + np;
                int b = b0 + 2 * bb2;
                float2 i2 = unpack2(acc[0][np]);
                float2 f2 = unpack2(acc[1][np]);
                float2 g2 = unpack2(acc[2][np]);
                float2 o2 = unpack2(acc[3][np]);
                float2 cold = (t > 0) ? csub[bb2 * JT + jjl] : make_float2(0.f, 0.f);
                float2 cc, hh;
                cc.x = fmaf(siga(f2.x), cold.x, siga(i2.x) * tanha(g2.x));
                cc.y = fmaf(siga(f2.y), cold.y, siga(i2.y) * tanha(g2.y));
                hh.x = siga(o2.x) * tanha(cc.x);
                hh.y = siga(o2.y) * tanha(cc.y);
                csub[bb2 * JT + jjl] = cc;
                ht2[bb2 * HS2 + jjl] = hh;
                if (b < BATCH) {
                    out[((long)b * TSEQ + t) * HSZ + j0 + jjl] = hh.x;
                    out[((long)(b + 1) * TSEQ + t) * HSZ + j0 + jjl] = hh.y;
                    if (lastT && hdst) {
                        hdst[(long)b * HSZ + j0 + jjl] = hh.x;
                        hdst[(long)(b + 1) * HSZ + j0 + jjl] = hh.y;
                        cdst[(long)b * HSZ + j0 + jjl] = cc.x;
                        cdst[(long)(b + 1) * HSZ + j0 + jjl] = cc.y;
                    }
                }
            }
            __syncthreads();

            // ---- hu partials -> prt: (js 0-3, rh 0-1, bb 0-55) ----
            {
                const int js = tid >> 7, rh = (tid >> 6) & 1, bb = tid & 63;
                if (bb < NB) {
                    const float* htf = reinterpret_cast<const float*>(ht2);
                    ull a5[5];
#pragma unroll
                    for (int q = 0; q < 5; q++) a5[q] = 0ull;
                    const int jbeg = js * 32;
#pragma unroll 4
                    for (int jj = 0; jj < 32; jj++) {
                        int j = jbeg + jj;
                        float hv = htf[(bb >> 1) * (HS2 * 2) + j * 2 + (bb & 1)];
                        ull hs2v = pack2(hv, hv);
                        const float* wrow = wa + j * RNK + rh * 10;
#pragma unroll
                        for (int q = 0; q < 5; q++)
                            ffma2(a5[q], hs2v, *reinterpret_cast<const ull*>(wrow + 2 * q));
                    }
#pragma unroll
                    for (int q = 0; q < 5; q++)
                        prt[((rh * 5 + q) * 4 + js) * NB + bb] = a5[q];
                }
            }
            __syncthreads();

            // ---- reduce 4 jslices -> g_hu[r][jt][B] ----
            for (int o = tid; o < 640; o += 512) {
                int bb = o & 63, rp = o >> 6;
                if (bb < NB) {
                    int b = b0 + bb;
                    ull s = add2(add2(prt[(rp * 4 + 0) * NB + bb], prt[(rp * 4 + 1) * NB + bb]),
                                 add2(prt[(rp * 4 + 2) * NB + bb], prt[(rp * 4 + 3) * NB + bb]));
                    float2 f = unpack2(s);
                    if (b < BATCH) {
                        wr[((2 * rp + 0) * NJT + jt) * BATCH + b] = f.x;
                        wr[((2 * rp + 1) * NJT + jt) * BATCH + b] = f.y;
                    }
                }
            }
            // no trailing sync: prt/vsp2 next touched only after >=2 barriers
        }

        // all threads' g_hu writes must land before tid0 releases
        __syncthreads();
        if (t < TSEQ - 1 && tid == 0) bar_arrive(&g_bar);
    }
}

// ---------------------------------------------------------------------------
extern "C" void kernel_launch(void* const* d_in, const int* in_sizes, int n_in,
                              void* d_out, int out_size) {
    const float* x     = (const float*)d_in[0];
    const float* wih_a = (const float*)d_in[1];
    const float* wih_b = (const float*)d_in[2];
    const float* b_ih  = (const float*)d_in[3];
    const float* whh_a = (const float*)d_in[4];
    const float* whh_b = (const float*)d_in[5];
    const float* b_hh  = (const float*)d_in[6];
    float* out = (float*)d_out;

    const long BTH = (long)BATCH * TSEQ * HSZ;
    float* hdst = nullptr;
    float* cdst = nullptr;
    if ((long)out_size >= BTH + 2L * BATCH * HSZ) {
        hdst = out + BTH;
        cdst = hdst + (long)BATCH * HSZ;
    }

    cudaFuncSetAttribute(kPre, cudaFuncAttributeMaxDynamicSharedMemorySize,
                         KPRE_SMEM_FLOATS * 4);
    cudaFuncSetAttribute(kStep, cudaFuncAttributeMaxDynamicSharedMemorySize,
                         SMEM_FLOATS * 4);

    kPre<<<TSEQ * 16, 256, KPRE_SMEM_FLOATS * 4>>>(x, wih_a);
    kStep<<<NBLK, 512, SMEM_FLOATS * 4>>>(wih_b, b_ih, whh_a, whh_b, b_hh,
                                          out, hdst, cdst);
}

// round 16
// speedup vs baseline: 1.0026x; 1.0026x over previous
#include <cuda_runtime.h>

#define BATCH 4096
#define TSEQ  20
#define INSZ  512
#define HSZ   512
#define RNK   20
#define G4    2048
#define NB    56          // batch rows per sub-tile
#define NB2   28          // batch pairs per sub-tile
#define JT    128         // j columns per block
#define NJT   4
#define NBC   37
#define NBLK  (NJT * NBC) // 148 persistent blocks, all resident
#define HS2   129         // ht2 row stride (float2 units)
#define XCH   64          // kPre k-chunk
#define XSTR  66          // kPre xt row stride: bank stride 2 -> LDS.64 conflict-free

// Scratch (no allocations allowed -> device globals)
__device__ float g_u[TSEQ * RNK * BATCH];        // [t][r][b]
__device__ float g_hu[2][RNK * NJT * BATCH];     // [parity][r][jt][b]
__device__ unsigned g_bar;

typedef unsigned long long ull;

__device__ __forceinline__ void ffma2(ull &d, ull a, ull b) {
    asm("fma.rn.f32x2 %0, %1, %2, %0;" : "+l"(d) : "l"(a), "l"(b));
}
__device__ __forceinline__ ull add2(ull a, ull b) {
    ull d; asm("add.rn.f32x2 %0, %1, %2;" : "=l"(d) : "l"(a), "l"(b)); return d;
}
__device__ __forceinline__ ull pack2(float x, float y) {
    ull r; asm("mov.b64 %0, {%1, %2};" : "=l"(r) : "f"(x), "f"(y)); return r;
}
__device__ __forceinline__ float2 unpack2(ull v) {
    float2 f; asm("mov.b64 {%0, %1}, %2;" : "=f"(f.x), "=f"(f.y) : "l"(v)); return f;
}
__device__ __forceinline__ float tanha(float x) {
    float y; asm("tanh.approx.f32 %0, %1;" : "=f"(y) : "f"(x)); return y;
}
__device__ __forceinline__ float siga(float x) {
    return fmaf(tanha(0.5f * x), 0.5f, 0.5f);
}
__device__ __forceinline__ void bar_arrive(unsigned* p) {
    asm volatile("red.release.gpu.global.add.u32 [%0], 1;" :: "l"(p) : "memory");
}
__device__ __forceinline__ unsigned bar_peek(unsigned* p) {
    unsigned v;
    asm volatile("ld.acquire.gpu.global.u32 %0, [%1];" : "=r"(v) : "l"(p) : "memory");
    return v;
}

// ---------------------------------------------------------------------------
// kPre: u[t][r][b] = sum_k x[b][t][k] * wa[k][r]
// Block = one t x 256 consecutive b; k-chunks of 64 staged coalesced in smem.
// smem = 256*66 + 64*20 = 18176 floats = 72704 B -> 3 blocks/SM, 320 blocks = 1 wave.
#define KPRE_SMEM_FLOATS (256 * XSTR + XCH * RNK)

__global__ __launch_bounds__(256) void kPre(const float* __restrict__ x,
                                            const float* __restrict__ wa) {
    if (blockIdx.x == 0 && threadIdx.x == 0) g_bar = 0u;

    extern __shared__ __align__(16) float smp[];
    float* xt  = smp;                   // [256][XSTR]
    float* wch = smp + 256 * XSTR;      // [XCH][RNK]

    const int tid = threadIdx.x;
    const int t  = blockIdx.x >> 4;           // 16 blocks per t
    const int b0 = (blockIdx.x & 15) * 256;
    const float* xbase = x + ((long)b0 * TSEQ + t) * INSZ;

    ull acc[10];
#pragma unroll
    for (int q = 0; q < 10; q++) acc[q] = 0ull;

    for (int c = 0; c < INSZ / XCH; c++) {
        __syncthreads();    // xt & wch free
        // ---- coalesced x load: 16 lanes cover 256B of one row; 2x STS.64 ----
#pragma unroll
        for (int i = 0; i < 16; i++) {
            int idx = i * 256 + tid;          // float4 slot in [0, 4096)
            int row = idx >> 4, col4 = idx & 15;
            float4 v = *reinterpret_cast<const float4*>(
                xbase + (long)row * (TSEQ * INSZ) + c * XCH + col4 * 4);
            float* dst = xt + row * XSTR + col4 * 4;
            *reinterpret_cast<float2*>(dst)     = make_float2(v.x, v.y);
            *reinterpret_cast<float2*>(dst + 2) = make_float2(v.z, v.w);
        }
        // ---- was chunk: wch[k][r] (coalesced) ----
#pragma unroll
        for (int i = 0; i < 5; i++) {
            int idx = i * 256 + tid;          // [0, 1280)
            wch[idx] = wa[c * XCH * RNK + idx];
        }
        __syncthreads();
        // ---- compute: thread owns row tid; conflict-free LDS.64 ----
#pragma unroll 8
        for (int k2 = 0; k2 < XCH / 2; k2++) {
            float2 xv = *reinterpret_cast<const float2*>(xt + tid * XSTR + k2 * 2);
#pragma unroll
            for (int i = 0; i < 2; i++) {
                float kv = i ? xv.y : xv.x;
                ull ks = pack2(kv, kv);
                const ulonglong2* w2 = reinterpret_cast<const ulonglong2*>(
                    wch + (k2 * 2 + i) * RNK);
#pragma unroll
                for (int q = 0; q < 5; q++) {
                    ulonglong2 wv = w2[q];
                    ffma2(acc[2 * q + 0], ks, wv.x);
                    ffma2(acc[2 * q + 1], ks, wv.y);
                }
            }
        }
    }
    const int b = b0 + tid;
#pragma unroll
    for (int q = 0; q < 10; q++) {
        float2 f = unpack2(acc[q]);
        g_u[(t * RNK + 2 * q + 0) * BATCH + b] = f.x;
        g_u[(t * RNK + 2 * q + 1) * BATCH + b] = f.y;
    }
}

// ---------------------------------------------------------------------------
// kStep smem partition (floats)
#define WT_OFF   0
#define WT_SZ    (40 * 512)                 // wT[k][gate*128+jjl]  (persistent)
#define VS_OFF   (WT_OFF + WT_SZ)
#define VS_SZ    (40 * NB2 * 2)             // 2240: vsp2[k][bb2] ull (true pairs)
#define BS_OFF   (VS_OFF + VS_SZ)
#define BS_SZ    512                        // bias (persistent)
#define HT_OFF   (BS_OFF + BS_SZ)
#define HT_SZ    (NB2 * HS2 * 2)            // 7224: ht2[bb2][jjl] float2
#define WA_OFF   (HT_OFF + HT_SZ)
#define WA_SZ    (JT * RNK)                 // 2560: wa[j][r]  (persistent)
#define CS_OFF   (WA_OFF + WA_SZ)
#define CS_SZ    (2 * NB2 * JT * 2)         // 14336: c as float2 pairs, both subs
#define PR_OFF   (CS_OFF + CS_SZ)
#define PR_SZ    (40 * NB * 2)              // 4480: hu partials (ull)
#define SMEM_FLOATS (PR_OFF + PR_SZ)        // 51872 floats = 207488 B -> 1 block/SM

template<int K0, int K1>
__device__ __forceinline__ void gemm_part(ull (&acc)[4][7], const float* wT,
                                          const ull* vsp2, int jjl, int nt) {
#pragma unroll 4
    for (int k = K0; k < K1; k++) {
        float w0 = wT[k * 512 + 0 * 128 + jjl];
        float w1 = wT[k * 512 + 1 * 128 + jjl];
        float w2 = wT[k * 512 + 2 * 128 + jjl];
        float w3 = wT[k * 512 + 3 * 128 + jjl];
        ull wg[4] = {pack2(w0, w0), pack2(w1, w1), pack2(w2, w2), pack2(w3, w3)};
        ull vn[7];
#pragma unroll
        for (int n = 0; n < 7; n++) vn[n] = vsp2[k * NB2 + nt * 7 + n];
#pragma unroll
        for (int g = 0; g < 4; g++)
#pragma unroll
            for (int n = 0; n < 7; n++)
                ffma2(acc[g][n], wg[g], vn[n]);
    }
}

__global__ __launch_bounds__(512, 1) void kStep(
    const float* __restrict__ wih_b, const float* __restrict__ b_ih,
    const float* __restrict__ whh_a, const float* __restrict__ whh_b,
    const float* __restrict__ b_hh,
    float* __restrict__ out,
    float* __restrict__ hdst, float* __restrict__ cdst) {

    extern __shared__ __align__(16) float sm[];
    float* wT   = sm + WT_OFF;
    ull*   vsp2 = reinterpret_cast<ull*>(sm + VS_OFF);
    float* bs   = sm + BS_OFF;
    float2* ht2 = reinterpret_cast<float2*>(sm + HT_OFF);
    float* wa   = sm + WA_OFF;
    float2* cs2 = reinterpret_cast<float2*>(sm + CS_OFF);
    ull*   prt  = reinterpret_cast<ull*>(sm + PR_OFF);

    const int tid = threadIdx.x;
    const int jt = blockIdx.x & 3, bc = blockIdx.x >> 2;   // 4 x 37
    const int j0 = jt * JT;
    const int jjl = tid & 127, nt = tid >> 7;              // 128 x 4

    // ======== one-time staging ========
#pragma unroll
    for (int it = 0; it < 10; it++) {
        int idx4 = it * 512 + tid;
        int r = idx4 >> 7;
        int q = idx4 & 127;
        int gate = q >> 5, jjl4 = q & 31;
        const float* src = (r < RNK) ? (wih_b + r * G4) : (whh_b + (r - RNK) * G4);
        float4 v = reinterpret_cast<const float4*>(src + gate * 512 + j0)[jjl4];
        reinterpret_cast<float4*>(wT + r * 512 + gate * 128)[jjl4] = v;
    }
    {
        int gate = tid >> 7, jjlx = tid & 127;
        int col = gate * 512 + j0 + jjlx;
        bs[tid] = b_ih[col] + b_hh[col];
    }
    for (int idx = tid; idx < (JT * RNK) / 4; idx += 512)
        reinterpret_cast<float4*>(wa)[idx] =
            reinterpret_cast<const float4*>(whh_a + j0 * RNK)[idx];
    __syncthreads();

    // bias splats (constant over time loop)
    ull bgu[4];
#pragma unroll
    for (int g = 0; g < 4; g++) {
        float bv = bs[g * 128 + jjl];
        bgu[g] = pack2(bv, bv);
    }

    // ======== time loop ========
    for (int t = 0; t < TSEQ; t++) {
        const float* rd = g_hu[t & 1];
        float*       wr = g_hu[(t + 1) & 1];
        const bool lastT = (t == TSEQ - 1);

#pragma unroll 1
        for (int sub = 0; sub < 2; sub++) {
            const int b0 = bc * (2 * NB) + sub * NB;
            float2* csub = cs2 + sub * (NB2 * JT);

            // ---- stage u pairs (vsp2 rows 0..19) ----
            for (int idx = tid; idx < RNK * 32; idx += 512) {
                int r = idx >> 5, bb2 = idx & 31;
                if (bb2 < NB2) {
                    int b = b0 + 2 * bb2;
                    float2 v = make_float2(0.f, 0.f);
                    if (b < BATCH)
                        v = *reinterpret_cast<const float2*>(
                            &g_u[(t * RNK + r) * BATCH + b]);
                    vsp2[r * NB2 + bb2] = pack2(v.x, v.y);
                }
            }
            if (sub == 1) {
                for (int idx = tid; idx < RNK * 32; idx += 512) {
                    int r = idx >> 5, bb2 = idx & 31;
                    if (bb2 < NB2) {
                        int b = b0 + 2 * bb2;
                        float2 v = make_float2(0.f, 0.f);
                        if (t > 0 && b < BATCH) {
                            const float2* p = reinterpret_cast<const float2*>(
                                rd + r * (NJT * BATCH) + b);
                            float2 q0 = __ldcg(p);
                            float2 q1 = __ldcg(p + BATCH / 2);
                            float2 q2 = __ldcg(p + BATCH);
                            float2 q3 = __ldcg(p + 3 * BATCH / 2);
                            v = make_float2((q0.x + q1.x) + (q2.x + q3.x),
                                            (q0.y + q1.y) + (q2.y + q3.y));
                        }
                        vsp2[(RNK + r) * NB2 + bb2] = pack2(v.x, v.y);
                    }
                }
            }
            __syncthreads();

            // ---- GEMM (sub0: split around grid barrier; sub1: full) ----
            ull acc[4][7];
#pragma unroll
            for (int g = 0; g < 4; g++)
#pragma unroll
                for (int n = 0; n < 7; n++) acc[g][n] = bgu[g];

            if (sub == 0) {
                gemm_part<0, RNK>(acc, wT, vsp2, jjl, nt);   // u half, hides barrier
                if (t > 0 && tid == 0) {
                    unsigned target = (unsigned)NBLK * (unsigned)t;
                    while (bar_peek(&g_bar) < target) __nanosleep(64);
                }
                __syncthreads();
                // stage hu pairs (vsp2 rows 20..39)
                for (int idx = tid; idx < RNK * 32; idx += 512) {
                    int r = idx >> 5, bb2 = idx & 31;
                    if (bb2 < NB2) {
                        int b = b0 + 2 * bb2;
                        float2 v = make_float2(0.f, 0.f);
                        if (t > 0 && b < BATCH) {
                            const float2* p = reinterpret_cast<const float2*>(
                                rd + r * (NJT * BATCH) + b);
                            float2 q0 = __ldcg(p);
                            float2 q1 = __ldcg(p + BATCH / 2);
                            float2 q2 = __ldcg(p + BATCH);
                            float2 q3 = __ldcg(p + 3 * BATCH / 2);
                            v = make_float2((q0.x + q1.x) + (q2.x + q3.x),
                                            (q0.y + q1.y) + (q2.y + q3.y));
                        }
                        vsp2[(RNK + r) * NB2 + bb2] = pack2(v.x, v.y);
                    }
                }
                __syncthreads();
                gemm_part<RNK, 2 * RNK>(acc, wT, vsp2, jjl, nt);
            } else {
                gemm_part<0, 2 * RNK>(acc, wT, vsp2, jjl, nt);
            }

            // ---- epilogue: cell update over 7 (b, b+1) pairs ----
#pragma unroll
            for (int np = 0; np < 7; np++) {
                int bb2 = nt * 7 + np;
                int b = b0 + 2 * bb2;
                float2 i2 = unpack2(acc[0][np]);
                float2 f2 = unpack2(acc[1][np]);
                float2 g2 = unpack2(acc[2][np]);
                float2 o2 = unpack2(acc[3][np]);
                float2 cold = (t > 0) ? csub[bb2 * JT + jjl] : make_float2(0.f, 0.f);
                float2 cc, hh;
                cc.x = fmaf(siga(f2.x), cold.x, siga(i2.x) * tanha(g2.x));
                cc.y = fmaf(siga(f2.y), cold.y, siga(i2.y) * tanha(g2.y));
                hh.x = siga(o2.x) * tanha(cc.x);
                hh.y = siga(o2.y) * tanha(cc.y);
                csub[bb2 * JT + jjl] = cc;
                ht2[bb2 * HS2 + jjl] = hh;
                if (b < BATCH) {
                    out[((long)b * TSEQ + t) * HSZ + j0 + jjl] = hh.x;
                    out[((long)(b + 1) * TSEQ + t) * HSZ + j0 + jjl] = hh.y;
                    if (lastT && hdst) {
                        hdst[(long)b * HSZ + j0 + jjl] = hh.x;
                        hdst[(long)(b + 1) * HSZ + j0 + jjl] = hh.y;
                        cdst[(long)b * HSZ + j0 + jjl] = cc.x;
                        cdst[(long)(b + 1) * HSZ + j0 + jjl] = cc.y;
                    }
                }
            }
            __syncthreads();

            // ---- hu partials -> prt: (js 0-3, rh 0-1, bb 0-55) ----
            {
                const int js = tid >> 7, rh = (tid >> 6) & 1, bb = tid & 63;
                if (bb < NB) {
                    const float* htf = reinterpret_cast<const float*>(ht2);
                    ull a5[5];
#pragma unroll
                    for (int q = 0; q < 5; q++) a5[q] = 0ull;
                    const int jbeg = js * 32;
#pragma unroll 4
                    for (int jj = 0; jj < 32; jj++) {
                        int j = jbeg + jj;
                        float hv = htf[(bb >> 1) * (HS2 * 2) + j * 2 + (bb & 1)];
                        ull hs2v = pack2(hv, hv);
                        const float* wrow = wa + j * RNK + rh * 10;
#pragma unroll
                        for (int q = 0; q < 5; q++)
                            ffma2(a5[q], hs2v, *reinterpret_cast<const ull*>(wrow + 2 * q));
                    }
#pragma unroll
                    for (int q = 0; q < 5; q++)
                        prt[((rh * 5 + q) * 4 + js) * NB + bb] = a5[q];
                }
            }
            __syncthreads();

            // ---- reduce 4 jslices -> g_hu[r][jt][B] ----
            for (int o = tid; o < 640; o += 512) {
                int bb = o & 63, rp = o >> 6;
                if (bb < NB) {
                    int b = b0 + bb;
                    ull s = add2(add2(prt[(rp * 4 + 0) * NB + bb], prt[(rp * 4 + 1) * NB + bb]),
                                 add2(prt[(rp * 4 + 2) * NB + bb], prt[(rp * 4 + 3) * NB + bb]));
                    float2 f = unpack2(s);
                    if (b < BATCH) {
                        wr[((2 * rp + 0) * NJT + jt) * BATCH + b] = f.x;
                        wr[((2 * rp + 1) * NJT + jt) * BATCH + b] = f.y;
                    }
                }
            }
            // no trailing sync: prt/vsp2 next touched only after >=2 barriers
        }

        // all threads' g_hu writes must land before tid0 releases
        __syncthreads();
        if (t < TSEQ - 1 && tid == 0) bar_arrive(&g_bar);
    }
}

// ---------------------------------------------------------------------------
extern "C" void kernel_launch(void* const* d_in, const int* in_sizes, int n_in,
                              void* d_out, int out_size) {
    const float* x     = (const float*)d_in[0];
    const float* wih_a = (const float*)d_in[1];
    const float* wih_b = (const float*)d_in[2];
    const float* b_ih  = (const float*)d_in[3];
    const float* whh_a = (const float*)d_in[4];
    const float* whh_b = (const float*)d_in[5];
    const float* b_hh  = (const float*)d_in[6];
    float* out = (float*)d_out;

    const long BTH = (long)BATCH * TSEQ * HSZ;
    float* hdst = nullptr;
    float* cdst = nullptr;
    if ((long)out_size >= BTH + 2L * BATCH * HSZ) {
        hdst = out + BTH;
        cdst = hdst + (long)BATCH * HSZ;
    }

    cudaFuncSetAttribute(kPre, cudaFuncAttributeMaxDynamicSharedMemorySize,
                         KPRE_SMEM_FLOATS * 4);
    cudaFuncSetAttribute(kStep, cudaFuncAttributeMaxDynamicSharedMemorySize,
                         SMEM_FLOATS * 4);

    kPre<<<TSEQ * 16, 256, KPRE_SMEM_FLOATS * 4>>>(x, wih_a);
    kStep<<<NBLK, 512, SMEM_FLOATS * 4>>>(wih_b, b_ih, whh_a, whh_b, b_hh,
                                          out, hdst, cdst);
}

// round 17
// speedup vs baseline: 1.0126x; 1.0099x over previous
#include <cuda_runtime.h>

#define BATCH 4096
#define TSEQ  20
#define INSZ  512
#define HSZ   512
#define RNK   20
#define G4    2048
#define NB    56          // batch rows per sub-tile
#define NB2   28          // batch pairs per sub-tile
#define JT    128         // j columns per block
#define NJT   4
#define NBC   37
#define NBLK  (NJT * NBC) // 148 persistent blocks, all resident
#define HS2   129         // ht2 row stride (float2 units)
#define XCH   64          // u-prologue k-chunk
#define XSTR  66          // u-prologue xt row stride
#define RPB   554         // u rows per block (148*554 >= 81920)

// Scratch (no allocations allowed -> device globals)
__device__ float g_u[TSEQ * RNK * BATCH];        // [t][r][b]
__device__ float g_hu[2][RNK * NJT * BATCH];     // [parity][r][jt][b]
__device__ unsigned g_bar;

typedef unsigned long long ull;

__device__ __forceinline__ void ffma2(ull &d, ull a, ull b) {
    asm("fma.rn.f32x2 %0, %1, %2, %0;" : "+l"(d) : "l"(a), "l"(b));
}
__device__ __forceinline__ ull add2(ull a, ull b) {
    ull d; asm("add.rn.f32x2 %0, %1, %2;" : "=l"(d) : "l"(a), "l"(b)); return d;
}
__device__ __forceinline__ ull pack2(float x, float y) {
    ull r; asm("mov.b64 %0, {%1, %2};" : "=l"(r) : "f"(x), "f"(y)); return r;
}
__device__ __forceinline__ float2 unpack2(ull v) {
    float2 f; asm("mov.b64 {%0, %1}, %2;" : "=f"(f.x), "=f"(f.y) : "l"(v)); return f;
}
__device__ __forceinline__ float tanha(float x) {
    float y; asm("tanh.approx.f32 %0, %1;" : "=f"(y) : "f"(x)); return y;
}
__device__ __forceinline__ float siga(float x) {
    return fmaf(tanha(0.5f * x), 0.5f, 0.5f);
}
__device__ __forceinline__ void bar_arrive(unsigned* p) {
    asm volatile("red.release.gpu.global.add.u32 [%0], 1;" :: "l"(p) : "memory");
}
__device__ __forceinline__ unsigned bar_peek(unsigned* p) {
    unsigned v;
    asm volatile("ld.acquire.gpu.global.u32 %0, [%1];" : "=r"(v) : "l"(p) : "memory");
    return v;
}

// ---------------------------------------------------------------------------
__global__ void kZ() { g_bar = 0u; }

// ---------------------------------------------------------------------------
// kStep smem partition (floats). Prologue overlays xt/wch on [0, 35072).
#define WT_OFF   0
#define WT_SZ    (40 * 512)                 // wT[k][gate*128+jjl]  (persistent)
#define VS_OFF   (WT_OFF + WT_SZ)
#define VS_SZ    (40 * NB2 * 2)             // 2240: vsp2[k][bb2] ull (true pairs)
#define BS_OFF   (VS_OFF + VS_SZ)
#define BS_SZ    512                        // bias (persistent)
#define HT_OFF   (BS_OFF + BS_SZ)
#define HT_SZ    (NB2 * HS2 * 2)            // 7224: ht2[bb2][jjl] float2
#define WA_OFF   (HT_OFF + HT_SZ)
#define WA_SZ    (JT * RNK)                 // 2560: wa[j][r]  (persistent)
#define CS_OFF   (WA_OFF + WA_SZ)
#define CS_SZ    (2 * NB2 * JT * 2)         // 14336: c as float2 pairs, both subs
#define PR_OFF   (CS_OFF + CS_SZ)
#define PR_SZ    (40 * NB * 2)              // 4480: hu partials (ull)
#define SMEM_FLOATS (PR_OFF + PR_SZ)        // 51872 floats = 207488 B -> 1 block/SM

template<int K0, int K1>
__device__ __forceinline__ void gemm_part(ull (&acc)[4][7], const float* wT,
                                          const ull* vsp2, int jjl, int nt) {
#pragma unroll 4
    for (int k = K0; k < K1; k++) {
        float w0 = wT[k * 512 + 0 * 128 + jjl];
        float w1 = wT[k * 512 + 1 * 128 + jjl];
        float w2 = wT[k * 512 + 2 * 128 + jjl];
        float w3 = wT[k * 512 + 3 * 128 + jjl];
        ull wg[4] = {pack2(w0, w0), pack2(w1, w1), pack2(w2, w2), pack2(w3, w3)};
        ull vn[7];
#pragma unroll
        for (int n = 0; n < 7; n++) vn[n] = vsp2[k * NB2 + nt * 7 + n];
#pragma unroll
        for (int g = 0; g < 4; g++)
#pragma unroll
            for (int n = 0; n < 7; n++)
                ffma2(acc[g][n], wg[g], vn[n]);
    }
}

__global__ __launch_bounds__(512, 1) void kStep(
    const float* __restrict__ x, const float* __restrict__ wih_a,
    const float* __restrict__ wih_b, const float* __restrict__ b_ih,
    const float* __restrict__ whh_a, const float* __restrict__ whh_b,
    const float* __restrict__ b_hh,
    float* __restrict__ out,
    float* __restrict__ hdst, float* __restrict__ cdst) {

    extern __shared__ __align__(16) float sm[];
    float* wT   = sm + WT_OFF;
    ull*   vsp2 = reinterpret_cast<ull*>(sm + VS_OFF);
    float* bs   = sm + BS_OFF;
    float2* ht2 = reinterpret_cast<float2*>(sm + HT_OFF);
    float* wa   = sm + WA_OFF;
    float2* cs2 = reinterpret_cast<float2*>(sm + CS_OFF);
    ull*   prt  = reinterpret_cast<ull*>(sm + PR_OFF);

    const int tid = threadIdx.x;
    const int jt = blockIdx.x & 3, bc = blockIdx.x >> 2;   // 4 x 37
    const int j0 = jt * JT;
    const int jjl = tid & 127, nt = tid >> 7;              // 128 x 4

    // ======== u prologue: rows [blk*RPB, blk*RPB+RPB) of (b,t) space ========
    {
        float* xt  = sm;                  // [512][XSTR] (overlays wT region)
        float* wch = sm + 512 * XSTR;     // [XCH][RNK]
        const int rbeg = blockIdx.x * RPB;
        const int rend = min(rbeg + RPB, TSEQ * BATCH);

        for (int R0 = rbeg; R0 < rend; R0 += 512) {
            const int nr = rend - R0 < 512 ? rend - R0 : 512;
            ull acc[10];
#pragma unroll
            for (int q = 0; q < 10; q++) acc[q] = 0ull;

            for (int c = 0; c < INSZ / XCH; c++) {
                __syncthreads();
                // stage x chunk: coalesced (16 lanes cover 256B of one row)
#pragma unroll
                for (int i = 0; i < 16; i++) {
                    int idx = i * 512 + tid;
                    int row = idx >> 4, c4 = idx & 15;
                    if (row < nr) {
                        float4 v = *reinterpret_cast<const float4*>(
                            x + (long)(R0 + row) * INSZ + c * XCH + c4 * 4);
                        float* dst = xt + row * XSTR + c4 * 4;
                        *reinterpret_cast<float2*>(dst)     = make_float2(v.x, v.y);
                        *reinterpret_cast<float2*>(dst + 2) = make_float2(v.z, v.w);
                    }
                }
                for (int i = tid; i < XCH * RNK; i += 512)
                    wch[i] = wih_a[c * XCH * RNK + i];
                __syncthreads();
                if (tid < nr) {
#pragma unroll 8
                    for (int k2 = 0; k2 < XCH / 2; k2++) {
                        float2 xv = *reinterpret_cast<const float2*>(
                            xt + tid * XSTR + k2 * 2);
#pragma unroll
                        for (int i = 0; i < 2; i++) {
                            float kv = i ? xv.y : xv.x;
                            ull ks = pack2(kv, kv);
                            const ulonglong2* w2 = reinterpret_cast<const ulonglong2*>(
                                wch + (k2 * 2 + i) * RNK);
#pragma unroll
                            for (int q = 0; q < 5; q++) {
                                ulonglong2 wv = w2[q];
                                ffma2(acc[2 * q + 0], ks, wv.x);
                                ffma2(acc[2 * q + 1], ks, wv.y);
                            }
                        }
                    }
                }
            }
            if (tid < nr) {
                int rho = R0 + tid;
                int b = rho / TSEQ, t = rho % TSEQ;
#pragma unroll
                for (int q = 0; q < 10; q++) {
                    float2 f = unpack2(acc[q]);
                    g_u[(t * RNK + 2 * q + 0) * BATCH + b] = f.x;
                    g_u[(t * RNK + 2 * q + 1) * BATCH + b] = f.y;
                }
            }
        }
        __syncthreads();
        if (tid == 0) bar_arrive(&g_bar);        // phase 0: u published
    }
    __syncthreads();

    // ======== one-time staging (overwrites prologue scratch) ========
#pragma unroll
    for (int it = 0; it < 10; it++) {
        int idx4 = it * 512 + tid;
        int r = idx4 >> 7;
        int q = idx4 & 127;
        int gate = q >> 5, jjl4 = q & 31;
        const float* src = (r < RNK) ? (wih_b + r * G4) : (whh_b + (r - RNK) * G4);
        float4 v = reinterpret_cast<const float4*>(src + gate * 512 + j0)[jjl4];
        reinterpret_cast<float4*>(wT + r * 512 + gate * 128)[jjl4] = v;
    }
    {
        int gate = tid >> 7, jjlx = tid & 127;
        int col = gate * 512 + j0 + jjlx;
        bs[tid] = b_ih[col] + b_hh[col];
    }
    for (int idx = tid; idx < (JT * RNK) / 4; idx += 512)
        reinterpret_cast<float4*>(wa)[idx] =
            reinterpret_cast<const float4*>(whh_a + j0 * RNK)[idx];
    __syncthreads();

    // wait for u of ALL blocks (hidden behind weight staging)
    if (tid == 0) {
        while (bar_peek(&g_bar) < (unsigned)NBLK) __nanosleep(64);
    }
    __syncthreads();

    // bias splats (constant over time loop)
    ull bgu[4];
#pragma unroll
    for (int g = 0; g < 4; g++) {
        float bv = bs[g * 128 + jjl];
        bgu[g] = pack2(bv, bv);
    }

    // ======== time loop ========
    for (int t = 0; t < TSEQ; t++) {
        const float* rd = g_hu[t & 1];
        float*       wr = g_hu[(t + 1) & 1];
        const bool lastT = (t == TSEQ - 1);

#pragma unroll 1
        for (int sub = 0; sub < 2; sub++) {
            const int b0 = bc * (2 * NB) + sub * NB;
            float2* csub = cs2 + sub * (NB2 * JT);

            // ---- stage u pairs (vsp2 rows 0..19) ----
            for (int idx = tid; idx < RNK * 32; idx += 512) {
                int r = idx >> 5, bb2 = idx & 31;
                if (bb2 < NB2) {
                    int b = b0 + 2 * bb2;
                    float2 v = make_float2(0.f, 0.f);
                    if (b < BATCH)
                        v = *reinterpret_cast<const float2*>(
                            &g_u[(t * RNK + r) * BATCH + b]);
                    vsp2[r * NB2 + bb2] = pack2(v.x, v.y);
                }
            }
            if (sub == 1) {
                for (int idx = tid; idx < RNK * 32; idx += 512) {
                    int r = idx >> 5, bb2 = idx & 31;
                    if (bb2 < NB2) {
                        int b = b0 + 2 * bb2;
                        float2 v = make_float2(0.f, 0.f);
                        if (t > 0 && b < BATCH) {
                            const float2* p = reinterpret_cast<const float2*>(
                                rd + r * (NJT * BATCH) + b);
                            float2 q0 = __ldcg(p);
                            float2 q1 = __ldcg(p + BATCH / 2);
                            float2 q2 = __ldcg(p + BATCH);
                            float2 q3 = __ldcg(p + 3 * BATCH / 2);
                            v = make_float2((q0.x + q1.x) + (q2.x + q3.x),
                                            (q0.y + q1.y) + (q2.y + q3.y));
                        }
                        vsp2[(RNK + r) * NB2 + bb2] = pack2(v.x, v.y);
                    }
                }
            }
            __syncthreads();

            // ---- GEMM (sub0: split around grid barrier; sub1: full) ----
            ull acc[4][7];
#pragma unroll
            for (int g = 0; g < 4; g++)
#pragma unroll
                for (int n = 0; n < 7; n++) acc[g][n] = bgu[g];

            if (sub == 0) {
                gemm_part<0, RNK>(acc, wT, vsp2, jjl, nt);   // u half, hides barrier
                if (t > 0 && tid == 0) {
                    unsigned target = (unsigned)NBLK * (unsigned)(t + 1);
                    while (bar_peek(&g_bar) < target) __nanosleep(64);
                }
                __syncthreads();
                // stage hu pairs (vsp2 rows 20..39)
                for (int idx = tid; idx < RNK * 32; idx += 512) {
                    int r = idx >> 5, bb2 = idx & 31;
                    if (bb2 < NB2) {
                        int b = b0 + 2 * bb2;
                        float2 v = make_float2(0.f, 0.f);
                        if (t > 0 && b < BATCH) {
                            const float2* p = reinterpret_cast<const float2*>(
                                rd + r * (NJT * BATCH) + b);
                            float2 q0 = __ldcg(p);
                            float2 q1 = __ldcg(p + BATCH / 2);
                            float2 q2 = __ldcg(p + BATCH);
                            float2 q3 = __ldcg(p + 3 * BATCH / 2);
                            v = make_float2((q0.x + q1.x) + (q2.x + q3.x),
                                            (q0.y + q1.y) + (q2.y + q3.y));
                        }
                        vsp2[(RNK + r) * NB2 + bb2] = pack2(v.x, v.y);
                    }
                }
                __syncthreads();
                gemm_part<RNK, 2 * RNK>(acc, wT, vsp2, jjl, nt);
            } else {
                gemm_part<0, 2 * RNK>(acc, wT, vsp2, jjl, nt);
            }

            // ---- epilogue: cell update over 7 (b, b+1) pairs ----
#pragma unroll
            for (int np = 0; np < 7; np++) {
                int bb2 = nt * 7 + np;
                int b = b0 + 2 * bb2;
                float2 i2 = unpack2(acc[0][np]);
                float2 f2 = unpack2(acc[1][np]);
                float2 g2 = unpack2(acc[2][np]);
                float2 o2 = unpack2(acc[3][np]);
                float2 cold = (t > 0) ? csub[bb2 * JT + jjl] : make_float2(0.f, 0.f);
                float2 cc, hh;
                cc.x = fmaf(siga(f2.x), cold.x, siga(i2.x) * tanha(g2.x));
                cc.y = fmaf(siga(f2.y), cold.y, siga(i2.y) * tanha(g2.y));
                hh.x = siga(o2.x) * tanha(cc.x);
                hh.y = siga(o2.y) * tanha(cc.y);
                csub[bb2 * JT + jjl] = cc;
                ht2[bb2 * HS2 + jjl] = hh;
                if (b < BATCH) {
                    out[((long)b * TSEQ + t) * HSZ + j0 + jjl] = hh.x;
                    out[((long)(b + 1) * TSEQ + t) * HSZ + j0 + jjl] = hh.y;
                    if (lastT && hdst) {
                        hdst[(long)b * HSZ + j0 + jjl] = hh.x;
                        hdst[(long)(b + 1) * HSZ + j0 + jjl] = hh.y;
                        cdst[(long)b * HSZ + j0 + jjl] = cc.x;
                        cdst[(long)(b + 1) * HSZ + j0 + jjl] = cc.y;
                    }
                }
            }
            __syncthreads();

            // ---- hu partials -> prt: (js 0-3, rh 0-1, bb 0-55) ----
            {
                const int js = tid >> 7, rh = (tid >> 6) & 1, bb = tid & 63;
                if (bb < NB) {
                    const float* htf = reinterpret_cast<const float*>(ht2);
                    ull a5[5];
#pragma unroll
                    for (int q = 0; q < 5; q++) a5[q] = 0ull;
                    const int jbeg = js * 32;
#pragma unroll 4
                    for (int jj = 0; jj < 32; jj++) {
                        int j = jbeg + jj;
                        float hv = htf[(bb >> 1) * (HS2 * 2) + j * 2 + (bb & 1)];
                        ull hs2v = pack2(hv, hv);
                        const float* wrow = wa + j * RNK + rh * 10;
#pragma unroll
                        for (int q = 0; q < 5; q++)
                            ffma2(a5[q], hs2v, *reinterpret_cast<const ull*>(wrow + 2 * q));
                    }
#pragma unroll
                    for (int q = 0; q < 5; q++)
                        prt[((rh * 5 + q) * 4 + js) * NB + bb] = a5[q];
                }
            }
            __syncthreads();

            // ---- reduce 4 jslices -> g_hu[r][jt][B] ----
            for (int o = tid; o < 640; o += 512) {
                int bb = o & 63, rp = o >> 6;
                if (bb < NB) {
                    int b = b0 + bb;
                    ull s = add2(add2(prt[(rp * 4 + 0) * NB + bb], prt[(rp * 4 + 1) * NB + bb]),
                                 add2(prt[(rp * 4 + 2) * NB + bb], prt[(rp * 4 + 3) * NB + bb]));
                    float2 f = unpack2(s);
                    if (b < BATCH) {
                        wr[((2 * rp + 0) * NJT + jt) * BATCH + b] = f.x;
                        wr[((2 * rp + 1) * NJT + jt) * BATCH + b] = f.y;
                    }
                }
            }
            // no trailing sync: prt/vsp2 next touched only after >=2 barriers
        }

        // all threads' g_hu writes must land before tid0 releases
        __syncthreads();
        if (t < TSEQ - 1 && tid == 0) bar_arrive(&g_bar);
    }
}

// ---------------------------------------------------------------------------
extern "C" void kernel_launch(void* const* d_in, const int* in_sizes, int n_in,
                              void* d_out, int out_size) {
    const float* x     = (const float*)d_in[0];
    const float* wih_a = (const float*)d_in[1];
    const float* wih_b = (const float*)d_in[2];
    const float* b_ih  = (const float*)d_in[3];
    const float* whh_a = (const float*)d_in[4];
    const float* whh_b = (const float*)d_in[5];
    const float* b_hh  = (const float*)d_in[6];
    float* out = (float*)d_out;

    const long BTH = (long)BATCH * TSEQ * HSZ;
    float* hdst = nullptr;
    float* cdst = nullptr;
    if ((long)out_size >= BTH + 2L * BATCH * HSZ) {
        hdst = out + BTH;
        cdst = hdst + (long)BATCH * HSZ;
    }

    cudaFuncSetAttribute(kStep, cudaFuncAttributeMaxDynamicSharedMemorySize,
                         SMEM_FLOATS * 4);

    kZ<<<1, 1>>>();
    kStep<<<NBLK, 512, SMEM_FLOATS * 4>>>(x, wih_a, wih_b, b_ih, whh_a, whh_b,
                                          b_hh, out, hdst, cdst);
}